// round 16
// baseline (speedup 1.0000x reference)
#include <cuda_runtime.h>
#include <cuda_fp16.h>
#include <math.h>
#include <float.h>
#include <stdint.h>

// ---------------------------------------------------------------------------
// Problem constants
// ---------------------------------------------------------------------------
#define D        768
#define HW       1024
#define NB       4
#define NQ       4096
#define NDB      20000
#define OUT_H    512
#define OUT_W    512

// GEMM tiling: CTA 128x128, 8 warps (4M x 2N), warp tile 32x64, fp16 acc
#define TM       128
#define TN       128
#define KT       64              // fp16 K per stage (128 B/row)
#define NKC      (D / KT)        // 12 K-stages
#define NPAD     20096           // 157 * 128
#define NTN      (NPAD / TN)     // 157
#define NQT      (NQ / TM)       // 32
#define NSLOT    (NTN * 2)       // partial slots per query (2 warp halves in N)

// SMEM: rows padded to 144B -> conflict-free ldmatrix, 16B aligned
#define PITCH        144
#define A_BYTES      (TM * PITCH)           // 18432
#define STAGE_BYTES  (2 * A_BYTES)          // A + B = 36864
#define NSTAGE       3
#define SM_TOTAL     (NSTAGE * STAGE_BYTES) // 110592

// Prep kernel split
#define DB_BLOCKS    2500                   // 8 rows per block -> 20000 rows
#define EMB_BLOCKS   3072                   // (D/32) * (HW/32) * NB

// ---------------------------------------------------------------------------
// Scratch (device globals — zero-initialized at load; padded B rows stay 0)
// ---------------------------------------------------------------------------
__device__ __half g_Ah[NQ * D];                // ~6.3 MB
__device__ __half g_Bh[NPAD * D];              // ~31 MB
__device__ float g_x2[NDB];
__device__ float g_p0[(size_t)NQ * NSLOT];     // SoA partial planes
__device__ float g_p1[(size_t)NQ * NSLOT];
__device__ float g_p2[(size_t)NQ * NSLOT];
__device__ float g_ood[NQ];

// ---------------------------------------------------------------------------
// Helpers
// ---------------------------------------------------------------------------
__device__ __forceinline__ uint32_t smem_to_u32(const void* p) {
    uint32_t a;
    asm("{ .reg .u64 t; cvta.to.shared.u64 t, %1; cvt.u32.u64 %0, t; }"
        : "=r"(a) : "l"(p));
    return a;
}

__device__ __forceinline__ void cp_async16(uint32_t dst, const void* src) {
    asm volatile("cp.async.cg.shared.global [%0], [%1], 16;"
                 :: "r"(dst), "l"(src) : "memory");
}
#define CP_COMMIT() asm volatile("cp.async.commit_group;" ::: "memory")
#define CP_WAIT_1() asm volatile("cp.async.wait_group 1;" ::: "memory")
#define CP_WAIT_0() asm volatile("cp.async.wait_group 0;" ::: "memory")

__device__ __forceinline__ void ldsm_x4(uint32_t& r0, uint32_t& r1,
                                        uint32_t& r2, uint32_t& r3,
                                        uint32_t addr) {
    asm volatile("ldmatrix.sync.aligned.m8n8.x4.shared.b16 {%0,%1,%2,%3}, [%4];"
                 : "=r"(r0), "=r"(r1), "=r"(r2), "=r"(r3) : "r"(addr));
}

// fp16 MMA with fp16 accumulators: C fragment is 2 regs (half2 x2)
__device__ __forceinline__ void mma_h16(uint32_t* c, const uint32_t* a,
                                        const uint32_t* b) {
    asm volatile(
        "mma.sync.aligned.m16n8k16.row.col.f16.f16.f16.f16 "
        "{%0,%1}, {%2,%3,%4,%5}, {%6,%7}, {%0,%1};"
        : "+r"(c[0]), "+r"(c[1])
        : "r"(a[0]), "r"(a[1]), "r"(a[2]), "r"(a[3]), "r"(b[0]), "r"(b[1]));
}

__device__ __forceinline__ void insert3(float s, float& b0, float& b1, float& b2) {
    if (s < b2) {
        if (s < b1) {
            b2 = b1;
            if (s < b0) { b1 = b0; b0 = s; }
            else        { b1 = s; }
        } else {
            b2 = s;
        }
    }
}

// ---------------------------------------------------------------------------
// Fused preprocess: one launch, two jobs.
//  blocks [0, DB_BLOCKS):       db fp32 -> g_Bh fp16 + fp32 norms (8 rows/blk)
//  blocks [DB_BLOCKS, +EMB):    embeddings transpose-convert -> g_Ah
// ---------------------------------------------------------------------------
__global__ void __launch_bounds__(256) prep_kernel(const float* __restrict__ emb,
                                                   const float* __restrict__ db) {
    if (blockIdx.x < DB_BLOCKS) {
        int row  = blockIdx.x * 8 + (threadIdx.x >> 5);
        int lane = threadIdx.x & 31;
        __half2* dst = reinterpret_cast<__half2*>(g_Bh + (size_t)row * D);
        const float2* src = reinterpret_cast<const float2*>(db + (size_t)row * D);
        float s = 0.f;
        #pragma unroll
        for (int i = lane; i < D / 2; i += 32) {
            float2 f = src[i];
            s = fmaf(f.x, f.x, fmaf(f.y, f.y, s));
            dst[i] = __float22half2_rn(f);
        }
        #pragma unroll
        for (int o = 16; o; o >>= 1) s += __shfl_down_sync(0xffffffffu, s, o);
        if (lane == 0) g_x2[row] = s;
    } else {
        __shared__ float tile[32][33];
        int t  = blockIdx.x - DB_BLOCKS;
        int b  = t / 768;
        int r  = t - b * 768;
        int d0 = (r % 24) * 32;
        int p0 = (r / 24) * 32;
        int tx = threadIdx.x & 31;
        int ty = threadIdx.x >> 5;         // 0..7
        const float* e = emb + (size_t)b * D * HW;
        #pragma unroll
        for (int yy = 0; yy < 4; ++yy) {
            int y = ty + yy * 8;
            tile[y][tx] = e[(size_t)(d0 + y) * HW + p0 + tx];
        }
        __syncthreads();
        #pragma unroll
        for (int yy = 0; yy < 4; ++yy) {
            int y = ty + yy * 8;
            int q = b * HW + p0 + y;
            g_Ah[(size_t)q * D + d0 + tx] = __float2half_rn(tile[tx][y]);
        }
    }
}

// ---------------------------------------------------------------------------
// fp16 mma.sync GEMM (fp16 accum) + fused top-3 epilogue.
// CTA: 128 q x 128 n, 8 warps (4M x 2N), warp tile 32x64.
// K: 12 stages of 64; 3-stage cp.async pipeline; kk-level fragment pipeline
// (enabled by halved accumulator registers).
// ---------------------------------------------------------------------------
struct GemmCtx {
    uint32_t smem_u;
    const __half* Ag0;
    const __half* Bg0;
    int lr, lc;
    int a_row, a_kadd, b_row, b_kadd;
};

template <int BUF>
__device__ __forceinline__ void issue_load(const GemmCtx& c, int kc) {
    const uint32_t baseA = c.smem_u + BUF * STAGE_BYTES;
    const uint32_t baseB = baseA + A_BYTES;
    const __half* Asrc = c.Ag0 + kc * KT;
    const __half* Bsrc = c.Bg0 + kc * KT;
    #pragma unroll
    for (int i = 0; i < 4; ++i) {
        int r = c.lr + i * 32;
        cp_async16(baseA + r * PITCH + c.lc * 16, Asrc + (size_t)r * D + c.lc * 8);
    }
    #pragma unroll
    for (int i = 0; i < 4; ++i) {
        int r = c.lr + i * 32;
        cp_async16(baseB + r * PITCH + c.lc * 16, Bsrc + (size_t)r * D + c.lc * 8);
    }
    CP_COMMIT();
}

template <int BUF>
__device__ __forceinline__ void mma_stage(const GemmCtx& c,
                                          uint32_t acc[2][8][2]) {
    const uint32_t aBase = c.smem_u + BUF * STAGE_BYTES;
    const uint32_t bBase = aBase + A_BYTES;

    uint32_t aF[2][2][4];
    uint32_t bF[2][8][2];

    // fragment loader for one kk into pipe slot p (compile-time under unroll)
    auto load_k = [&](int p, int kk) {
        #pragma unroll
        for (int mt = 0; mt < 2; ++mt) {
            uint32_t addr = aBase + (c.a_row + mt * 16) * PITCH
                          + (kk * 16 + c.a_kadd) * 2;
            ldsm_x4(aF[p][mt][0], aF[p][mt][1], aF[p][mt][2], aF[p][mt][3], addr);
        }
        #pragma unroll
        for (int pp = 0; pp < 4; ++pp) {
            uint32_t addr = bBase + (c.b_row + pp * 16) * PITCH
                          + (kk * 16 + c.b_kadd) * 2;
            uint32_t r0, r1, r2, r3;
            ldsm_x4(r0, r1, r2, r3, addr);
            bF[p][2 * pp][0]     = r0;
            bF[p][2 * pp][1]     = r1;
            bF[p][2 * pp + 1][0] = r2;
            bF[p][2 * pp + 1][1] = r3;
        }
    };

    load_k(0, 0);
    #pragma unroll
    for (int kk = 0; kk < 4; ++kk) {
        const int cur = kk & 1;
        if (kk < 3) load_k(cur ^ 1, kk + 1);   // overlap next ldsm with MMAs
        #pragma unroll
        for (int mt = 0; mt < 2; ++mt)
            #pragma unroll
            for (int nt = 0; nt < 8; ++nt)
                mma_h16(acc[mt][nt], aF[cur][mt], bF[cur][nt]);
    }
}

template <int BUF>
__device__ __forceinline__ void do_stage(const GemmCtx& c,
                                         uint32_t acc[2][8][2], int s) {
    if (s + 1 < NKC) { CP_WAIT_1(); } else { CP_WAIT_0(); }
    __syncthreads();   // stage-s data visible; stage-(s-1) buffer drained
    constexpr int NBUF = (BUF + 2) % 3;
    if (s + 2 < NKC) issue_load<NBUF>(c, s + 2);
    mma_stage<BUF>(c, acc);
}

__global__ void __launch_bounds__(256, 2) knn_mma_kernel() {
    extern __shared__ char smem[];
    const int tid  = threadIdx.x;
    const int lane = tid & 31;
    const int wid  = tid >> 5;
    const int wm   = wid & 3;      // warp M position (0..3)
    const int wn   = wid >> 2;     // warp N position (0..1)

    const int q0 = blockIdx.x * TM;
    const int n0 = blockIdx.y * TN;

    GemmCtx c;
    c.smem_u = smem_to_u32(smem);
    c.Ag0    = g_Ah + (size_t)q0 * D;
    c.Bg0    = g_Bh + (size_t)n0 * D;
    c.lr     = tid >> 3;
    c.lc     = tid & 7;
    c.a_row  = wm * 32 + (lane & 15);
    c.a_kadd = (lane >> 4) * 8;
    c.b_row  = wn * 64 + ((lane >> 4) & 1) * 8 + (lane & 7);
    c.b_kadd = ((lane >> 3) & 1) * 8;

    uint32_t acc[2][8][2];
    #pragma unroll
    for (int mt = 0; mt < 2; ++mt)
        #pragma unroll
        for (int nt = 0; nt < 8; ++nt) {
            acc[mt][nt][0] = 0u;
            acc[mt][nt][1] = 0u;
        }

    issue_load<0>(c, 0);
    issue_load<1>(c, 1);

    #pragma unroll 1
    for (int sb = 0; sb < NKC; sb += 3) {
        do_stage<0>(c, acc, sb);
        do_stage<1>(c, acc, sb + 1);
        do_stage<2>(c, acc, sb + 2);
    }

    // -----------------------------------------------------------------------
    // Epilogue: s = ||x||^2 - 2*dot ; per-thread top3 ; quad merge ; SoA write
    // fp16 C fragment: reg0 = {(r,c),(r,c+1)}, reg1 = {(r+8,c),(r+8,c+1)}
    //  -> reg index == "half" (row group), lo/hi == j (column pair)
    // -----------------------------------------------------------------------
    const int lane4 = lane & 3;
    const int quad  = lane >> 2;

    float xn2[8][2];
    #pragma unroll
    for (int nt = 0; nt < 8; ++nt)
        #pragma unroll
        for (int j = 0; j < 2; ++j) {
            int n = n0 + wn * 64 + nt * 8 + lane4 * 2 + j;
            xn2[nt][j] = (n < NDB) ? g_x2[n] : FLT_MAX;
        }

    #pragma unroll
    for (int mt = 0; mt < 2; ++mt) {
        #pragma unroll
        for (int half = 0; half < 2; ++half) {
            float b0 = FLT_MAX, b1 = FLT_MAX, b2 = FLT_MAX;
            #pragma unroll
            for (int nt = 0; nt < 8; ++nt) {
                __half2 h = *reinterpret_cast<__half2*>(&acc[mt][nt][half]);
                float2 f = __half22float2(h);
                insert3(fmaf(-2.f, f.x, xn2[nt][0]), b0, b1, b2);
                insert3(fmaf(-2.f, f.y, xn2[nt][1]), b0, b1, b2);
            }
            #pragma unroll
            for (int o = 1; o <= 2; o <<= 1) {
                float t0 = __shfl_xor_sync(0xffffffffu, b0, o);
                float t1 = __shfl_xor_sync(0xffffffffu, b1, o);
                float t2 = __shfl_xor_sync(0xffffffffu, b2, o);
                insert3(t0, b0, b1, b2);
                insert3(t1, b0, b1, b2);
                insert3(t2, b0, b1, b2);
            }
            if (lane4 == 0) {
                int q = q0 + wm * 32 + mt * 16 + quad + half * 8;
                size_t slot = (size_t)q * NSLOT + blockIdx.y * 2 + wn;
                g_p0[slot] = b0;
                g_p1[slot] = b1;
                g_p2[slot] = b2;
            }
        }
    }
}

// ---------------------------------------------------------------------------
// Merge partials: block per query (128 threads), fused fp16 q-norm,
// SoA planes -> 3 independent coalesced load streams.
// ---------------------------------------------------------------------------
__global__ void __launch_bounds__(128) knn_merge_kernel() {
    __shared__ float sm[128][4];
    const int q   = blockIdx.x;
    const int tid = threadIdx.x;

    // query norm partial from fp16 row (matches GEMM operand precision)
    const __half2* row =
        reinterpret_cast<const __half2*>(g_Ah + (size_t)q * D);
    float s = 0.f;
    #pragma unroll
    for (int i = tid; i < D / 2; i += 128) {
        float2 f = __half22float2(row[i]);
        s = fmaf(f.x, f.x, fmaf(f.y, f.y, s));
    }

    const size_t base = (size_t)q * NSLOT;
    float b0 = FLT_MAX, b1 = FLT_MAX, b2 = FLT_MAX;
    #pragma unroll 2
    for (int i = tid; i < NSLOT; i += 128) {
        float v0 = g_p0[base + i];
        float v1 = g_p1[base + i];
        float v2 = g_p2[base + i];
        insert3(v0, b0, b1, b2);
        insert3(v1, b0, b1, b2);
        insert3(v2, b0, b1, b2);
    }

    sm[tid][0] = b0; sm[tid][1] = b1; sm[tid][2] = b2; sm[tid][3] = s;
    __syncthreads();

    if (tid < 32) {
        float qs = sm[tid][3];
        b0 = sm[tid][0]; b1 = sm[tid][1]; b2 = sm[tid][2];
        #pragma unroll
        for (int k = 32; k < 128; k += 32) {
            qs += sm[tid + k][3];
            insert3(sm[tid + k][0], b0, b1, b2);
            insert3(sm[tid + k][1], b0, b1, b2);
            insert3(sm[tid + k][2], b0, b1, b2);
        }
        #pragma unroll
        for (int o = 16; o; o >>= 1) {
            qs += __shfl_xor_sync(0xffffffffu, qs, o);
            float t0 = __shfl_xor_sync(0xffffffffu, b0, o);
            float t1 = __shfl_xor_sync(0xffffffffu, b1, o);
            float t2 = __shfl_xor_sync(0xffffffffu, b2, o);
            insert3(t0, b0, b1, b2);
            insert3(t1, b0, b1, b2);
            insert3(t2, b0, b1, b2);
        }
        if (tid == 0) {
            float d0 = sqrtf(fmaxf(qs + b0, 1e-12f));
            float d1 = sqrtf(fmaxf(qs + b1, 1e-12f));
            float d2 = sqrtf(fmaxf(qs + b2, 1e-12f));
            g_ood[q] = (d0 + d1 + d2) * (1.f / 3.f);
        }
    }
}

// ---------------------------------------------------------------------------
// Bilinear upsample 32x32 -> 512x512 (half-pixel, edge-clamped), float4 out
// ---------------------------------------------------------------------------
__global__ void upsample_kernel(float* __restrict__ out) {
    int v = blockIdx.x * blockDim.x + threadIdx.x;     // float4 index
    if (v >= NB * OUT_H * OUT_W / 4) return;
    int b   = v >> 16;
    int rem = v & 65535;
    int oy  = rem >> 7;
    int ox0 = (rem & 127) * 4;

    const float inv = 1.f / 16.f;
    float sy = (oy + 0.5f) * inv - 0.5f;
    float fy0 = floorf(sy);
    float fy = sy - fy0;
    int y0 = (int)fy0;
    int y0c = min(max(y0, 0), 31);
    int y1c = min(max(y0 + 1, 0), 31);

    const float* o = &g_ood[b * HW];
    float4 r;
    float* rr = &r.x;
    #pragma unroll
    for (int j = 0; j < 4; ++j) {
        int ox = ox0 + j;
        float sx = (ox + 0.5f) * inv - 0.5f;
        float fx0 = floorf(sx);
        float fx = sx - fx0;
        int x0 = (int)fx0;
        int x0c = min(max(x0, 0), 31);
        int x1c = min(max(x0 + 1, 0), 31);
        float v00 = o[y0c * 32 + x0c];
        float v01 = o[y0c * 32 + x1c];
        float v10 = o[y1c * 32 + x0c];
        float v11 = o[y1c * 32 + x1c];
        float top = v00 + (v01 - v00) * fx;
        float bot = v10 + (v11 - v10) * fx;
        rr[j] = top + (bot - top) * fy;
    }
    reinterpret_cast<float4*>(out)[v] = r;
}

// ---------------------------------------------------------------------------
extern "C" void kernel_launch(void* const* d_in, const int* in_sizes, int n_in,
                              void* d_out, int out_size) {
    const float* emb = (const float*)d_in[0];   // [4, 768, 32, 32]
    const float* db  = (const float*)d_in[1];   // [20000, 768]
    float* out = (float*)d_out;                 // [4, 1, 512, 512]

    cudaFuncSetAttribute(knn_mma_kernel,
                         cudaFuncAttributeMaxDynamicSharedMemorySize, SM_TOTAL);

    prep_kernel<<<DB_BLOCKS + EMB_BLOCKS, 256>>>(emb, db);

    dim3 grid(NQT, NTN);
    knn_mma_kernel<<<grid, 256, SM_TOTAL>>>();

    knn_merge_kernel<<<NQ, 128>>>();
    upsample_kernel<<<(NB * OUT_H * OUT_W / 4 + 255) / 256, 256>>>(out);
}

// round 17
// speedup vs baseline: 1.0863x; 1.0863x over previous
#include <cuda_runtime.h>
#include <cuda_bf16.h>
#include <math.h>
#include <float.h>
#include <stdint.h>

// ---------------------------------------------------------------------------
// Problem constants
// ---------------------------------------------------------------------------
#define D        768
#define HW       1024
#define NB       4
#define NQ       4096
#define NDB      20000
#define OUT_H    512
#define OUT_W    512

// GEMM tiling: CTA 128x128, 8 warps (4M x 2N), warp tile 32x64
#define TM       128
#define TN       128
#define KT       64              // bf16 K per stage
#define NKC      12              // K-stages (D / KT)
#define NPAD     20096           // 157 * 128
#define NTN      (NPAD / TN)     // 157
#define NQT      (NQ / TM)       // 32
#define NSLOT    (NTN * 2)       // partial slots per query (2 warp halves in N)

// SMEM: rows padded to 144B -> conflict-free ldmatrix, 16B aligned
#define PITCH        144
#define A_BYTES      (TM * PITCH)           // 18432
#define STAGE_BYTES  (2 * A_BYTES)          // A + B = 36864
#define NSTAGE       3
#define SM_TOTAL     (NSTAGE * STAGE_BYTES) // 110592

// Prep kernel split
#define DB_BLOCKS    2500                   // 8 rows per block -> 20000 rows
#define EMB_BLOCKS   3072                   // (D/32) * (HW/32) * NB

// ---------------------------------------------------------------------------
// Scratch (device globals — zero-initialized at load; padded B rows stay 0)
// ---------------------------------------------------------------------------
__device__ __nv_bfloat16 g_Abf[NQ * D];        // ~6.3 MB
__device__ __nv_bfloat16 g_Bbf[NPAD * D];      // ~31 MB
__device__ float g_x2[NDB];
__device__ float g_p0[(size_t)NQ * NSLOT];     // SoA partial planes
__device__ float g_p1[(size_t)NQ * NSLOT];
__device__ float g_p2[(size_t)NQ * NSLOT];
__device__ float g_ood[NQ];

// ---------------------------------------------------------------------------
// Helpers
// ---------------------------------------------------------------------------
__device__ __forceinline__ uint32_t smem_to_u32(const void* p) {
    uint32_t a;
    asm("{ .reg .u64 t; cvta.to.shared.u64 t, %1; cvt.u32.u64 %0, t; }"
        : "=r"(a) : "l"(p));
    return a;
}

__device__ __forceinline__ void cp_async16(uint32_t dst, const void* src) {
    asm volatile("cp.async.cg.shared.global [%0], [%1], 16;"
                 :: "r"(dst), "l"(src) : "memory");
}
#define CP_COMMIT() asm volatile("cp.async.commit_group;" ::: "memory")
#define CP_WAIT_1() asm volatile("cp.async.wait_group 1;" ::: "memory")
#define CP_WAIT_0() asm volatile("cp.async.wait_group 0;" ::: "memory")

__device__ __forceinline__ void ldsm_x4(uint32_t& r0, uint32_t& r1,
                                        uint32_t& r2, uint32_t& r3,
                                        uint32_t addr) {
    asm volatile("ldmatrix.sync.aligned.m8n8.x4.shared.b16 {%0,%1,%2,%3}, [%4];"
                 : "=r"(r0), "=r"(r1), "=r"(r2), "=r"(r3) : "r"(addr));
}

__device__ __forceinline__ void mma_bf16(float* c, const uint32_t* a,
                                         const uint32_t* b) {
    asm volatile(
        "mma.sync.aligned.m16n8k16.row.col.f32.bf16.bf16.f32 "
        "{%0,%1,%2,%3}, {%4,%5,%6,%7}, {%8,%9}, {%0,%1,%2,%3};"
        : "+f"(c[0]), "+f"(c[1]), "+f"(c[2]), "+f"(c[3])
        : "r"(a[0]), "r"(a[1]), "r"(a[2]), "r"(a[3]), "r"(b[0]), "r"(b[1]));
}

__device__ __forceinline__ void insert3(float s, float& b0, float& b1, float& b2) {
    if (s < b2) {
        if (s < b1) {
            b2 = b1;
            if (s < b0) { b1 = b0; b0 = s; }
            else        { b1 = s; }
        } else {
            b2 = s;
        }
    }
}

// ---------------------------------------------------------------------------
// Fused preprocess: one launch, two jobs.
//  blocks [0, DB_BLOCKS):       db fp32 -> g_Bbf bf16 + fp32 norms (8 rows/blk)
//  blocks [DB_BLOCKS, +EMB):    embeddings transpose-convert -> g_Abf
// ---------------------------------------------------------------------------
__global__ void __launch_bounds__(256) prep_kernel(const float* __restrict__ emb,
                                                   const float* __restrict__ db) {
    if (blockIdx.x < DB_BLOCKS) {
        int row  = blockIdx.x * 8 + (threadIdx.x >> 5);
        int lane = threadIdx.x & 31;
        __nv_bfloat162* dst =
            reinterpret_cast<__nv_bfloat162*>(g_Bbf + (size_t)row * D);
        const float2* src = reinterpret_cast<const float2*>(db + (size_t)row * D);
        float s = 0.f;
        #pragma unroll
        for (int i = lane; i < D / 2; i += 32) {
            float2 f = src[i];
            s = fmaf(f.x, f.x, fmaf(f.y, f.y, s));
            dst[i] = __floats2bfloat162_rn(f.x, f.y);
        }
        #pragma unroll
        for (int o = 16; o; o >>= 1) s += __shfl_down_sync(0xffffffffu, s, o);
        if (lane == 0) g_x2[row] = s;
    } else {
        __shared__ float tile[32][33];
        int t  = blockIdx.x - DB_BLOCKS;
        int b  = t / 768;
        int r  = t - b * 768;
        int d0 = (r % 24) * 32;
        int p0 = (r / 24) * 32;
        int tx = threadIdx.x & 31;
        int ty = threadIdx.x >> 5;         // 0..7
        const float* e = emb + (size_t)b * D * HW;
        #pragma unroll
        for (int yy = 0; yy < 4; ++yy) {
            int y = ty + yy * 8;
            tile[y][tx] = e[(size_t)(d0 + y) * HW + p0 + tx];
        }
        __syncthreads();
        #pragma unroll
        for (int yy = 0; yy < 4; ++yy) {
            int y = ty + yy * 8;
            int q = b * HW + p0 + y;
            g_Abf[(size_t)q * D + d0 + tx] = __float2bfloat16(tile[tx][y]);
        }
    }
}

// ---------------------------------------------------------------------------
// bf16 mma.sync GEMM + fused top-3 epilogue.
// CTA: 128 q x 128 n, 8 warps (4M x 2N), warp tile 32x64.
// K: 12 FULLY-UNROLLED stages of 64; 3-stage cp.async pipeline; every stage
// index, buffer base, and wait depth is a compile-time constant.
// ---------------------------------------------------------------------------
struct GemmCtx {
    uint32_t smem_u;
    const __nv_bfloat16* Ag0;
    const __nv_bfloat16* Bg0;
    int lr, lc;
    int a_row, a_kadd, b_row, b_kadd;
};

template <int BUF>
__device__ __forceinline__ void issue_load(const GemmCtx& c, int kc) {
    const uint32_t baseA = c.smem_u + BUF * STAGE_BYTES;
    const uint32_t baseB = baseA + A_BYTES;
    const __nv_bfloat16* Asrc = c.Ag0 + kc * KT;
    const __nv_bfloat16* Bsrc = c.Bg0 + kc * KT;
    #pragma unroll
    for (int i = 0; i < 4; ++i) {
        int r = c.lr + i * 32;
        cp_async16(baseA + r * PITCH + c.lc * 16, Asrc + (size_t)r * D + c.lc * 8);
    }
    #pragma unroll
    for (int i = 0; i < 4; ++i) {
        int r = c.lr + i * 32;
        cp_async16(baseB + r * PITCH + c.lc * 16, Bsrc + (size_t)r * D + c.lc * 8);
    }
    CP_COMMIT();
}

template <int BUF>
__device__ __forceinline__ void mma_stage(const GemmCtx& c, float acc[2][8][4]) {
    const uint32_t aBase = c.smem_u + BUF * STAGE_BYTES;
    const uint32_t bBase = aBase + A_BYTES;
    #pragma unroll
    for (int kk = 0; kk < 4; ++kk) {
        uint32_t aF[2][4];
        #pragma unroll
        for (int mt = 0; mt < 2; ++mt) {
            uint32_t addr = aBase + (c.a_row + mt * 16) * PITCH
                          + (kk * 16 + c.a_kadd) * 2;
            ldsm_x4(aF[mt][0], aF[mt][1], aF[mt][2], aF[mt][3], addr);
        }
        uint32_t bF[8][2];
        #pragma unroll
        for (int p = 0; p < 4; ++p) {
            uint32_t addr = bBase + (c.b_row + p * 16) * PITCH
                          + (kk * 16 + c.b_kadd) * 2;
            uint32_t r0, r1, r2, r3;
            ldsm_x4(r0, r1, r2, r3, addr);
            bF[2 * p][0]     = r0;
            bF[2 * p][1]     = r1;
            bF[2 * p + 1][0] = r2;
            bF[2 * p + 1][1] = r3;
        }
        #pragma unroll
        for (int mt = 0; mt < 2; ++mt)
            #pragma unroll
            for (int nt = 0; nt < 8; ++nt)
                mma_bf16(acc[mt][nt], aF[mt], bF[nt]);
    }
}

// Compile-time stage S: wait depth, next-load predicate, buffer bases all fold.
template <int S>
__device__ __forceinline__ void do_stage_ct(const GemmCtx& c, float acc[2][8][4]) {
    if constexpr (S + 1 < NKC) { CP_WAIT_1(); } else { CP_WAIT_0(); }
    __syncthreads();   // stage-S data visible; stage-(S-1) buffer drained
    if constexpr (S + 2 < NKC) issue_load<(S + 2) % 3>(c, S + 2);
    mma_stage<S % 3>(c, acc);
}

template <int S>
__device__ __forceinline__ void run_stages(const GemmCtx& c, float acc[2][8][4]) {
    if constexpr (S < NKC) {
        do_stage_ct<S>(c, acc);
        run_stages<S + 1>(c, acc);
    }
}

__global__ void __launch_bounds__(256, 2) knn_mma_kernel() {
    extern __shared__ char smem[];
    const int tid  = threadIdx.x;
    const int lane = tid & 31;
    const int wid  = tid >> 5;
    const int wm   = wid & 3;      // warp M position (0..3)
    const int wn   = wid >> 2;     // warp N position (0..1)

    const int q0 = blockIdx.x * TM;
    const int n0 = blockIdx.y * TN;

    GemmCtx c;
    c.smem_u = smem_to_u32(smem);
    c.Ag0    = g_Abf + (size_t)q0 * D;
    c.Bg0    = g_Bbf + (size_t)n0 * D;
    c.lr     = tid >> 3;
    c.lc     = tid & 7;
    c.a_row  = wm * 32 + (lane & 15);
    c.a_kadd = (lane >> 4) * 8;
    c.b_row  = wn * 64 + ((lane >> 4) & 1) * 8 + (lane & 7);
    c.b_kadd = ((lane >> 3) & 1) * 8;

    float acc[2][8][4];
    #pragma unroll
    for (int mt = 0; mt < 2; ++mt)
        #pragma unroll
        for (int nt = 0; nt < 8; ++nt)
            #pragma unroll
            for (int j = 0; j < 4; ++j) acc[mt][nt][j] = 0.f;

    issue_load<0>(c, 0);
    issue_load<1>(c, 1);

    run_stages<0>(c, acc);

    // -----------------------------------------------------------------------
    // Epilogue: s = ||x||^2 - 2*dot ; per-thread top3 ; quad merge ; SoA write
    // Fragment c: row = lane/4 (+8 for c2,c3), cols = (lane%4)*2 + {0,1}
    // -----------------------------------------------------------------------
    const int lane4 = lane & 3;
    const int quad  = lane >> 2;

    float xn2[8][2];
    #pragma unroll
    for (int nt = 0; nt < 8; ++nt)
        #pragma unroll
        for (int j = 0; j < 2; ++j) {
            int n = n0 + wn * 64 + nt * 8 + lane4 * 2 + j;
            xn2[nt][j] = (n < NDB) ? g_x2[n] : FLT_MAX;
        }

    #pragma unroll
    for (int mt = 0; mt < 2; ++mt) {
        #pragma unroll
        for (int half = 0; half < 2; ++half) {
            float b0 = FLT_MAX, b1 = FLT_MAX, b2 = FLT_MAX;
            #pragma unroll
            for (int nt = 0; nt < 8; ++nt) {
                #pragma unroll
                for (int j = 0; j < 2; ++j) {
                    float v = fmaf(-2.f, acc[mt][nt][half * 2 + j], xn2[nt][j]);
                    insert3(v, b0, b1, b2);
                }
            }
            #pragma unroll
            for (int o = 1; o <= 2; o <<= 1) {
                float t0 = __shfl_xor_sync(0xffffffffu, b0, o);
                float t1 = __shfl_xor_sync(0xffffffffu, b1, o);
                float t2 = __shfl_xor_sync(0xffffffffu, b2, o);
                insert3(t0, b0, b1, b2);
                insert3(t1, b0, b1, b2);
                insert3(t2, b0, b1, b2);
            }
            if (lane4 == 0) {
                int q = q0 + wm * 32 + mt * 16 + quad + half * 8;
                size_t slot = (size_t)q * NSLOT + blockIdx.y * 2 + wn;
                g_p0[slot] = b0;
                g_p1[slot] = b1;
                g_p2[slot] = b2;
            }
        }
    }
}

// ---------------------------------------------------------------------------
// Merge partials: block per query (128 threads), fused bf16 q-norm,
// SoA planes -> 3 independent coalesced load streams.
// ---------------------------------------------------------------------------
__global__ void __launch_bounds__(128) knn_merge_kernel() {
    __shared__ float sm[128][4];
    const int q   = blockIdx.x;
    const int tid = threadIdx.x;

    // query norm partial from bf16 row (matches GEMM operand precision)
    const __nv_bfloat162* row =
        reinterpret_cast<const __nv_bfloat162*>(g_Abf + (size_t)q * D);
    float s = 0.f;
    #pragma unroll
    for (int i = tid; i < D / 2; i += 128) {
        float2 f = __bfloat1622float2(row[i]);
        s = fmaf(f.x, f.x, fmaf(f.y, f.y, s));
    }

    const size_t base = (size_t)q * NSLOT;
    float b0 = FLT_MAX, b1 = FLT_MAX, b2 = FLT_MAX;
    #pragma unroll 2
    for (int i = tid; i < NSLOT; i += 128) {
        float v0 = g_p0[base + i];
        float v1 = g_p1[base + i];
        float v2 = g_p2[base + i];
        insert3(v0, b0, b1, b2);
        insert3(v1, b0, b1, b2);
        insert3(v2, b0, b1, b2);
    }

    sm[tid][0] = b0; sm[tid][1] = b1; sm[tid][2] = b2; sm[tid][3] = s;
    __syncthreads();

    if (tid < 32) {
        float qs = sm[tid][3];
        b0 = sm[tid][0]; b1 = sm[tid][1]; b2 = sm[tid][2];
        #pragma unroll
        for (int k = 32; k < 128; k += 32) {
            qs += sm[tid + k][3];
            insert3(sm[tid + k][0], b0, b1, b2);
            insert3(sm[tid + k][1], b0, b1, b2);
            insert3(sm[tid + k][2], b0, b1, b2);
        }
        #pragma unroll
        for (int o = 16; o; o >>= 1) {
            qs += __shfl_xor_sync(0xffffffffu, qs, o);
            float t0 = __shfl_xor_sync(0xffffffffu, b0, o);
            float t1 = __shfl_xor_sync(0xffffffffu, b1, o);
            float t2 = __shfl_xor_sync(0xffffffffu, b2, o);
            insert3(t0, b0, b1, b2);
            insert3(t1, b0, b1, b2);
            insert3(t2, b0, b1, b2);
        }
        if (tid == 0) {
            float d0 = sqrtf(fmaxf(qs + b0, 1e-12f));
            float d1 = sqrtf(fmaxf(qs + b1, 1e-12f));
            float d2 = sqrtf(fmaxf(qs + b2, 1e-12f));
            g_ood[q] = (d0 + d1 + d2) * (1.f / 3.f);
        }
    }
}

// ---------------------------------------------------------------------------
// Bilinear upsample 32x32 -> 512x512 (half-pixel, edge-clamped), float4 out
// ---------------------------------------------------------------------------
__global__ void upsample_kernel(float* __restrict__ out) {
    int v = blockIdx.x * blockDim.x + threadIdx.x;     // float4 index
    if (v >= NB * OUT_H * OUT_W / 4) return;
    int b   = v >> 16;
    int rem = v & 65535;
    int oy  = rem >> 7;
    int ox0 = (rem & 127) * 4;

    const float inv = 1.f / 16.f;
    float sy = (oy + 0.5f) * inv - 0.5f;
    float fy0 = floorf(sy);
    float fy = sy - fy0;
    int y0 = (int)fy0;
    int y0c = min(max(y0, 0), 31);
    int y1c = min(max(y0 + 1, 0), 31);

    const float* o = &g_ood[b * HW];
    float4 r;
    float* rr = &r.x;
    #pragma unroll
    for (int j = 0; j < 4; ++j) {
        int ox = ox0 + j;
        float sx = (ox + 0.5f) * inv - 0.5f;
        float fx0 = floorf(sx);
        float fx = sx - fx0;
        int x0 = (int)fx0;
        int x0c = min(max(x0, 0), 31);
        int x1c = min(max(x0 + 1, 0), 31);
        float v00 = o[y0c * 32 + x0c];
        float v01 = o[y0c * 32 + x1c];
        float v10 = o[y1c * 32 + x0c];
        float v11 = o[y1c * 32 + x1c];
        float top = v00 + (v01 - v00) * fx;
        float bot = v10 + (v11 - v10) * fx;
        rr[j] = top + (bot - top) * fy;
    }
    reinterpret_cast<float4*>(out)[v] = r;
}

// ---------------------------------------------------------------------------
extern "C" void kernel_launch(void* const* d_in, const int* in_sizes, int n_in,
                              void* d_out, int out_size) {
    const float* emb = (const float*)d_in[0];   // [4, 768, 32, 32]
    const float* db  = (const float*)d_in[1];   // [20000, 768]
    float* out = (float*)d_out;                 // [4, 1, 512, 512]

    cudaFuncSetAttribute(knn_mma_kernel,
                         cudaFuncAttributeMaxDynamicSharedMemorySize, SM_TOTAL);

    prep_kernel<<<DB_BLOCKS + EMB_BLOCKS, 256>>>(emb, db);

    dim3 grid(NQT, NTN);
    knn_mma_kernel<<<grid, 256, SM_TOTAL>>>();

    knn_merge_kernel<<<NQ, 128>>>();
    upsample_kernel<<<(NB * OUT_H * OUT_W / 4 + 255) / 256, 256>>>(out);
}